// round 5
// baseline (speedup 1.0000x reference)
#include <cuda_runtime.h>

// Problem constants
#define BSZ   4
#define SDIM  1024
#define DDIM  1024
#define HN    16
#define DKN   64
#define NEGV  1e12f

// Scratch: qw | kw | vw | o  each [B*H, S, 64] or [B*S, 1024] = 4M floats.
#define SEG (1u << 22)
__device__ float g_scratch[4u * (1u << 22)];

// ---------------------------------------------------------------------------
// 64x64x16 tiled SGEMM: C[M,N] = A[M,K] * W[K,N] + bias, M=4096, N=K=1024.
// MODE 0: scatter to head-major layout g_scratch (for Q/K/V projections)
// MODE 1: row-major output with per-row q_mask multiply (final projection)
// ---------------------------------------------------------------------------
template <int MODE>
__global__ void __launch_bounds__(256) gemm64(
    const float* __restrict__ Aext, unsigned aOff,
    const float* __restrict__ W, const float* __restrict__ bias,
    const int* __restrict__ qmask,
    float* __restrict__ Cext, unsigned cOff)
{
    const int K = 1024, N = 1024;
    const float* A = Aext ? Aext : (g_scratch + aOff);
    float* C = Cext ? Cext : (g_scratch + cOff);

    __shared__ float As[16][64];  // [k][m] (transposed)
    __shared__ float Bs[16][64];  // [k][n]

    int tid = threadIdx.x;
    int tx = tid & 15, ty = tid >> 4;
    int m0 = blockIdx.y << 6, n0 = blockIdx.x << 6;

    float acc[4][4] = {};

    int ar = tid >> 2;            // 0..63
    int ac = (tid & 3) << 2;      // 0,4,8,12
    int br = tid >> 4;            // 0..15
    int bc = (tid & 15) << 2;     // 0..60

    const float* Aptr = A + (size_t)(m0 + ar) * K + ac;
    const float* Wptr = W + (size_t)br * N + n0 + bc;

    for (int k0 = 0; k0 < K; k0 += 16) {
        float4 a = *(const float4*)(Aptr + k0);
        float4 w = *(const float4*)(Wptr + (size_t)k0 * N);
        __syncthreads();  // previous-iteration reads complete
        As[ac + 0][ar] = a.x;
        As[ac + 1][ar] = a.y;
        As[ac + 2][ar] = a.z;
        As[ac + 3][ar] = a.w;
        *(float4*)&Bs[br][bc] = w;
        __syncthreads();
#pragma unroll
        for (int kk = 0; kk < 16; kk++) {
            float4 av = *(const float4*)&As[kk][ty << 2];
            float4 bv = *(const float4*)&Bs[kk][tx << 2];
            float aa[4] = {av.x, av.y, av.z, av.w};
            float bb[4] = {bv.x, bv.y, bv.z, bv.w};
#pragma unroll
            for (int i = 0; i < 4; i++)
#pragma unroll
                for (int j = 0; j < 4; j++)
                    acc[i][j] = fmaf(aa[i], bb[j], acc[i][j]);
        }
    }

    float bs[4];
#pragma unroll
    for (int j = 0; j < 4; j++) bs[j] = bias[n0 + (tx << 2) + j];

    if (MODE == 0) {
        // scatter to [B*H, S, 64]; one head per block column (n0 multiple of 64)
        int h = n0 >> 6;
#pragma unroll
        for (int i = 0; i < 4; i++) {
            int m = m0 + (ty << 2) + i;
            int b = m >> 10, s = m & 1023;
            float4 c;
            c.x = acc[i][0] + bs[0];
            c.y = acc[i][1] + bs[1];
            c.z = acc[i][2] + bs[2];
            c.w = acc[i][3] + bs[3];
            *(float4*)&C[((size_t)((b * HN + h) * SDIM + s) << 6) + (tx << 2)] = c;
        }
    } else {
#pragma unroll
        for (int i = 0; i < 4; i++) {
            int m = m0 + (ty << 2) + i;
            float qm = (float)qmask[m];
            float4 c;
            c.x = (acc[i][0] + bs[0]) * qm;
            c.y = (acc[i][1] + bs[1]) * qm;
            c.z = (acc[i][2] + bs[2]) * qm;
            c.w = (acc[i][3] + bs[3]) * qm;
            *(float4*)&C[(size_t)m * N + n0 + (tx << 2)] = c;
        }
    }
}

// ---------------------------------------------------------------------------
// Causal masked attention, fp32 flash-style, matching reference additive-mask
// semantics exactly. Q/K/V in g_scratch as [B*H, S, 64].
// Degenerate rows (no unmasked visible key -> row max ~ -1e12) require a
// sweep over FUTURE tiles too, because the reference's additive -1e12 masks
// put causally-masked keys in the same fp32 max-class (s - 1e12 == -1e12
// exactly in fp32). A block-wide flag triggers that sweep; it only fires for
// the first few query rows (P = 2^-(row+1)), so it is ~free.
// ---------------------------------------------------------------------------
__global__ void __launch_bounds__(256) attn64(
    unsigned qOff, unsigned kOff, unsigned vOff, unsigned oOff,
    const int* __restrict__ vmask)
{
    __shared__ float Qs[64 * 64];   // transposed: Qs[d][qi]
    __shared__ float KPs[64 * 64];  // K transposed [d][key], reused as P [key][qi]
    __shared__ float Vs[64 * 64];   // natural [key][d]
    __shared__ int s_flag;

    int tid = threadIdx.x;
    int tx = tid & 15, ty = tid >> 4;
    int qt = blockIdx.x;            // q tile (16)
    int bh = blockIdx.y;            // b*H + h (64)
    int b = bh >> 4, h = bh & 15;

    const float* Qb = g_scratch + qOff + ((size_t)bh * SDIM << 6);
    const float* Kb = g_scratch + kOff + ((size_t)bh * SDIM << 6);
    const float* Vb = g_scratch + vOff + ((size_t)bh * SDIM << 6);

    if (tid == 0) s_flag = 0;

    // Load Q tile transposed
#pragma unroll
    for (int it = 0; it < 4; it++) {
        int idx = tid + it * 256;
        int row = idx >> 4;
        int d4 = (idx & 15) << 2;
        float4 f = *(const float4*)&Qb[((size_t)(qt * 64 + row) << 6) + d4];
        Qs[(d4 + 0) * 64 + row] = f.x;
        Qs[(d4 + 1) * 64 + row] = f.y;
        Qs[(d4 + 2) * 64 + row] = f.z;
        Qs[(d4 + 3) * 64 + row] = f.w;
    }

    float m_i[4], l_i[4], o_acc[4][4];
#pragma unroll
    for (int i = 0; i < 4; i++) {
        m_i[i] = -INFINITY;
        l_i[i] = 0.0f;
#pragma unroll
        for (int d = 0; d < 4; d++) o_acc[i][d] = 0.0f;
    }

    auto process_tile = [&](int kt) {
        __syncthreads();  // Q stores / previous P,V reads complete
        // Load K tile transposed, V tile natural
#pragma unroll
        for (int it = 0; it < 4; it++) {
            int idx = tid + it * 256;
            int row = idx >> 4;
            int d4 = (idx & 15) << 2;
            float4 kf = *(const float4*)&Kb[((size_t)(kt * 64 + row) << 6) + d4];
            KPs[(d4 + 0) * 64 + row] = kf.x;
            KPs[(d4 + 1) * 64 + row] = kf.y;
            KPs[(d4 + 2) * 64 + row] = kf.z;
            KPs[(d4 + 3) * 64 + row] = kf.w;
            float4 vf = *(const float4*)&Vb[((size_t)(kt * 64 + row) << 6) + d4];
            *(float4*)&Vs[row * 64 + d4] = vf;
        }
        __syncthreads();

        // S = Q K^T (64x64x64), each thread a 4x4 micro-tile
        float sacc[4][4] = {};
#pragma unroll
        for (int kk = 0; kk < 64; kk++) {
            float4 qa = *(const float4*)&Qs[kk * 64 + (ty << 2)];
            float4 ka = *(const float4*)&KPs[kk * 64 + (tx << 2)];
            float aa[4] = {qa.x, qa.y, qa.z, qa.w};
            float bb[4] = {ka.x, ka.y, ka.z, ka.w};
#pragma unroll
            for (int i = 0; i < 4; i++)
#pragma unroll
                for (int j = 0; j < 4; j++)
                    sacc[i][j] = fmaf(aa[i], bb[j], sacc[i][j]);
        }

        // Masks: EXACT reference semantics — additive -1e12 in fp32 for both
        // the v_mask and the causal mask.
        float vneg[4];
#pragma unroll
        for (int j = 0; j < 4; j++) {
            int key = kt * 64 + (tx << 2) + j;
            vneg[j] = vmask[b * SDIM + key] ? 0.0f : NEGV;
        }
#pragma unroll
        for (int i = 0; i < 4; i++) {
            int qrow = qt * 64 + (ty << 2) + i;
#pragma unroll
            for (int j = 0; j < 4; j++) {
                int key = kt * 64 + (tx << 2) + j;
                float s = sacc[i][j] * 0.125f - vneg[j];
                if (key > qrow) s -= NEGV;
                sacc[i][j] = s;
            }
        }

        // Online softmax (reduce across the 16 tx lanes sharing a row)
#pragma unroll
        for (int i = 0; i < 4; i++) {
            float tmax = fmaxf(fmaxf(sacc[i][0], sacc[i][1]),
                               fmaxf(sacc[i][2], sacc[i][3]));
#pragma unroll
            for (int off = 8; off >= 1; off >>= 1)
                tmax = fmaxf(tmax, __shfl_xor_sync(0xffffffffu, tmax, off));
            float mn = fmaxf(m_i[i], tmax);
            float corr = __expf(m_i[i] - mn);
            float rs = 0.0f;
#pragma unroll
            for (int j = 0; j < 4; j++) {
                float p = __expf(sacc[i][j] - mn);
                sacc[i][j] = p;
                rs += p;
            }
#pragma unroll
            for (int off = 8; off >= 1; off >>= 1)
                rs += __shfl_xor_sync(0xffffffffu, rs, off);
            l_i[i] = l_i[i] * corr + rs;
            m_i[i] = mn;
#pragma unroll
            for (int d = 0; d < 4; d++) o_acc[i][d] *= corr;
        }

        __syncthreads();  // everyone done reading K before overwrite with P
        // Store P transposed: KPs[key][qi]
#pragma unroll
        for (int i = 0; i < 4; i++)
#pragma unroll
            for (int j = 0; j < 4; j++)
                KPs[((tx << 2) + j) * 64 + (ty << 2) + i] = sacc[i][j];
        __syncthreads();

        // O += P V (64x64x64)
#pragma unroll
        for (int jj = 0; jj < 64; jj++) {
            float4 pa = *(const float4*)&KPs[jj * 64 + (ty << 2)];
            float4 va = *(const float4*)&Vs[jj * 64 + (tx << 2)];
            float pp[4] = {pa.x, pa.y, pa.z, pa.w};
            float vv[4] = {va.x, va.y, va.z, va.w};
#pragma unroll
            for (int i = 0; i < 4; i++)
#pragma unroll
                for (int d = 0; d < 4; d++)
                    o_acc[i][d] = fmaf(pp[i], vv[d], o_acc[i][d]);
        }
    };

    // Causal tiles
    for (int kt = 0; kt <= qt; kt++) process_tile(kt);

    // Degenerate-row detection: a row whose max is still ~ -1e12 has no
    // unmasked visible key; the reference then attends (uniformly, in fp32)
    // to the causally-masked future keys of the same max-class. Sweep the
    // remaining tiles for such blocks (rare: P(row j) = 2^-(j+1)).
    bool deg = false;
#pragma unroll
    for (int i = 0; i < 4; i++) deg |= (m_i[i] < -1e11f);
    if (deg) s_flag = 1;
    __syncthreads();
    if (s_flag) {
        for (int kt = qt + 1; kt < 16; kt++) process_tile(kt);
    }

    // Normalize and write o as [B*S, H*64]
    float* Ob = g_scratch + oOff;
#pragma unroll
    for (int i = 0; i < 4; i++) {
        int qrow = qt * 64 + (ty << 2) + i;
        float inv = 1.0f / l_i[i];
        float4 c;
        c.x = o_acc[i][0] * inv;
        c.y = o_acc[i][1] * inv;
        c.z = o_acc[i][2] * inv;
        c.w = o_acc[i][3] * inv;
        *(float4*)&Ob[((size_t)(b * SDIM + qrow) << 10) + (h << 6) + (tx << 2)] = c;
    }
}

// ---------------------------------------------------------------------------
extern "C" void kernel_launch(void* const* d_in, const int* in_sizes, int n_in,
                              void* d_out, int out_size)
{
    const float* q     = (const float*)d_in[0];
    const float* k     = (const float*)d_in[1];
    const float* v     = (const float*)d_in[2];
    const int*   vmask = (const int*)  d_in[3];
    const int*   qmask = (const int*)  d_in[4];
    // d_in[5] = a_mask (causal tril) -- implemented analytically
    const float* Wq = (const float*)d_in[6];
    const float* bq = (const float*)d_in[7];
    const float* Wk = (const float*)d_in[8];
    const float* bk = (const float*)d_in[9];
    const float* Wv = (const float*)d_in[10];
    const float* bv = (const float*)d_in[11];
    const float* Wo = (const float*)d_in[12];
    const float* bo = (const float*)d_in[13];
    float* out = (float*)d_out;

    const unsigned QW = 0u, KW = SEG, VW = 2u * SEG, OB = 3u * SEG;

    dim3 grid(16, 64), blk(256);
    gemm64<0><<<grid, blk>>>(q, 0u, Wq, bq, nullptr, nullptr, QW);
    gemm64<0><<<grid, blk>>>(k, 0u, Wk, bk, nullptr, nullptr, KW);
    gemm64<0><<<grid, blk>>>(v, 0u, Wv, bv, nullptr, nullptr, VW);
    attn64<<<dim3(16, 64), blk>>>(QW, KW, VW, OB, vmask);
    gemm64<1><<<grid, blk>>>(nullptr, OB, Wo, bo, qmask, out, 0u);
}

// round 6
// speedup vs baseline: 1.8462x; 1.8462x over previous
#include <cuda_runtime.h>

// Problem constants
#define BSZ   4
#define SDIM  1024
#define DDIM  1024
#define HN    16
#define DKN   64
#define NEGV  1e12f

// Scratch: qw | kw | vw | o  each [B*H, S, 64] or [B*S, 1024] = 4M floats.
#define SEG (1u << 22)
__device__ float g_scratch[4u * (1u << 22)];

// ---------------------------------------------------------------------------
// tf32 helpers
// ---------------------------------------------------------------------------
__device__ __forceinline__ unsigned f2tf(float x) {
    unsigned u;
    asm("cvt.rna.tf32.f32 %0, %1;" : "=r"(u) : "f"(x));
    return u;
}

__device__ __forceinline__ void mma_tf32(float c[4], const unsigned a[4],
                                         const unsigned b[2]) {
    asm volatile(
        "mma.sync.aligned.m16n8k8.row.col.f32.tf32.tf32.f32 "
        "{%0,%1,%2,%3},{%4,%5,%6,%7},{%8,%9},{%0,%1,%2,%3};\n"
        : "+f"(c[0]), "+f"(c[1]), "+f"(c[2]), "+f"(c[3])
        : "r"(a[0]), "r"(a[1]), "r"(a[2]), "r"(a[3]), "r"(b[0]), "r"(b[1]));
}

// ---------------------------------------------------------------------------
// tf32 tensor-core GEMM: C[M,N] = A[M,K]*W[K,N] + bias. M=4096, N=K=1024.
// Block tile 128x128, K-slab 16, 8 warps (4x2), warp tile 32x64 (2x8 mma).
// MODE 0: scatter to head-major layout g_scratch (Q/K/V projections)
// MODE 1: row-major output with per-row q_mask multiply (final projection)
// Smem padded strides: A stride 36 (bank=4m+k, conflict-free frag loads),
//                      B stride 136 (bank=8k+n, conflict-free frag loads).
// ---------------------------------------------------------------------------
template <int MODE>
__global__ void __launch_bounds__(256, 2) gemmTC(
    const float* __restrict__ Aext, unsigned aOff,
    const float* __restrict__ W, const float* __restrict__ bias,
    const int* __restrict__ qmask,
    float* __restrict__ Cext, unsigned cOff)
{
    const int K = 1024, N = 1024;
    const float* A = Aext ? Aext : (g_scratch + aOff);
    float* C = Cext ? Cext : (g_scratch + cOff);

    __shared__ __align__(16) unsigned As[128][36];
    __shared__ __align__(16) unsigned Bs[16][136];

    int tid = threadIdx.x;
    int lane = tid & 31, wid = tid >> 5;
    int wm = (wid & 3) << 5;       // warp m offset (0,32,64,96)
    int wn = (wid >> 2) << 6;      // warp n offset (0,64)
    int m0 = blockIdx.y << 7, n0 = blockIdx.x << 7;

    float c[2][8][4] = {};

    // Global load mapping (512 float4 per tile, 2 per thread)
    int arow[2], acol[2], brow[2], bcol[2];
#pragma unroll
    for (int i = 0; i < 2; i++) {
        int idx = tid + i * 256;
        arow[i] = idx >> 2;          // 0..127
        acol[i] = (idx & 3) << 2;    // 0,4,8,12
        brow[i] = idx >> 5;          // 0..15
        bcol[i] = (idx & 31) << 2;   // 0..124
    }

    float4 pa[2], pb[2];
#pragma unroll
    for (int i = 0; i < 2; i++) {
        pa[i] = *(const float4*)&A[(size_t)(m0 + arow[i]) * K + acol[i]];
        pb[i] = *(const float4*)&W[(size_t)brow[i] * N + n0 + bcol[i]];
    }

    for (int k0 = 0; k0 < K; k0 += 16) {
        __syncthreads();  // previous slab's frag reads complete
#pragma unroll
        for (int i = 0; i < 2; i++) {
            *(uint4*)&As[arow[i]][acol[i]] =
                make_uint4(f2tf(pa[i].x), f2tf(pa[i].y), f2tf(pa[i].z), f2tf(pa[i].w));
            *(uint4*)&Bs[brow[i]][bcol[i]] =
                make_uint4(f2tf(pb[i].x), f2tf(pb[i].y), f2tf(pb[i].z), f2tf(pb[i].w));
        }
        __syncthreads();

        // Prefetch next slab (latency hidden under mma issue)
        if (k0 + 16 < K) {
#pragma unroll
            for (int i = 0; i < 2; i++) {
                pa[i] = *(const float4*)&A[(size_t)(m0 + arow[i]) * K + k0 + 16 + acol[i]];
                pb[i] = *(const float4*)&W[(size_t)(k0 + 16 + brow[i]) * N + n0 + bcol[i]];
            }
        }

        int r = lane >> 2, cl = lane & 3;
#pragma unroll
        for (int ks = 0; ks < 16; ks += 8) {
            unsigned af[2][4], bf[8][2];
#pragma unroll
            for (int mt = 0; mt < 2; mt++) {
                int ar = wm + (mt << 4) + r;
                af[mt][0] = As[ar][ks + cl];
                af[mt][1] = As[ar + 8][ks + cl];
                af[mt][2] = As[ar][ks + 4 + cl];
                af[mt][3] = As[ar + 8][ks + 4 + cl];
            }
#pragma unroll
            for (int nt = 0; nt < 8; nt++) {
                int bn = wn + (nt << 3) + r;
                bf[nt][0] = Bs[ks + cl][bn];
                bf[nt][1] = Bs[ks + 4 + cl][bn];
            }
#pragma unroll
            for (int mt = 0; mt < 2; mt++)
#pragma unroll
                for (int nt = 0; nt < 8; nt++)
                    mma_tf32(c[mt][nt], af[mt], bf[nt]);
        }
    }

    // Epilogue: c frag mapping c0/c1 -> (row, 2*(lane&3)+{0,1}), c2/c3 -> row+8
    int r = lane >> 2, q2 = (lane & 3) << 1;
#pragma unroll
    for (int mt = 0; mt < 2; mt++) {
#pragma unroll
        for (int rr = 0; rr < 2; rr++) {
            int mrow = m0 + wm + (mt << 4) + r + (rr << 3);
            int bb = mrow >> 10, s = mrow & 1023;
            float qm = (MODE == 1) ? (float)qmask[mrow] : 1.0f;
#pragma unroll
            for (int nt = 0; nt < 8; nt++) {
                int nc = n0 + wn + (nt << 3) + q2;
                float v0 = c[mt][nt][rr * 2 + 0] + bias[nc];
                float v1 = c[mt][nt][rr * 2 + 1] + bias[nc + 1];
                if (MODE == 0) {
                    int h = nc >> 6, d = nc & 63;
                    float2 o; o.x = v0; o.y = v1;
                    *(float2*)&C[((size_t)((bb * HN + h) * SDIM + s) << 6) + d] = o;
                } else {
                    float2 o; o.x = v0 * qm; o.y = v1 * qm;
                    *(float2*)&C[(size_t)mrow * N + nc] = o;
                }
            }
        }
    }
}

// ---------------------------------------------------------------------------
// Causal masked attention, fp32 flash-style, matching reference additive-mask
// semantics exactly. Q/K/V in g_scratch as [B*H, S, 64].
// Degenerate rows (no unmasked visible key -> row max ~ -1e12) require a
// sweep over FUTURE tiles too (reference's additive -1e12 masks put causally-
// masked keys in the same fp32 max-class). Block-wide flag, fires rarely.
// ---------------------------------------------------------------------------
__global__ void __launch_bounds__(256) attn64(
    unsigned qOff, unsigned kOff, unsigned vOff, unsigned oOff,
    const int* __restrict__ vmask)
{
    __shared__ float Qs[64 * 64];   // transposed: Qs[d][qi]
    __shared__ float KPs[64 * 64];  // K transposed [d][key], reused as P [key][qi]
    __shared__ float Vs[64 * 64];   // natural [key][d]
    __shared__ int s_flag;

    int tid = threadIdx.x;
    int tx = tid & 15, ty = tid >> 4;
    int qt = blockIdx.x;            // q tile (16)
    int bh = blockIdx.y;            // b*H + h (64)
    int b = bh >> 4, h = bh & 15;

    const float* Qb = g_scratch + qOff + ((size_t)bh * SDIM << 6);
    const float* Kb = g_scratch + kOff + ((size_t)bh * SDIM << 6);
    const float* Vb = g_scratch + vOff + ((size_t)bh * SDIM << 6);

    if (tid == 0) s_flag = 0;

#pragma unroll
    for (int it = 0; it < 4; it++) {
        int idx = tid + it * 256;
        int row = idx >> 4;
        int d4 = (idx & 15) << 2;
        float4 f = *(const float4*)&Qb[((size_t)(qt * 64 + row) << 6) + d4];
        Qs[(d4 + 0) * 64 + row] = f.x;
        Qs[(d4 + 1) * 64 + row] = f.y;
        Qs[(d4 + 2) * 64 + row] = f.z;
        Qs[(d4 + 3) * 64 + row] = f.w;
    }

    float m_i[4], l_i[4], o_acc[4][4];
#pragma unroll
    for (int i = 0; i < 4; i++) {
        m_i[i] = -INFINITY;
        l_i[i] = 0.0f;
#pragma unroll
        for (int d = 0; d < 4; d++) o_acc[i][d] = 0.0f;
    }

    auto process_tile = [&](int kt) {
        __syncthreads();
#pragma unroll
        for (int it = 0; it < 4; it++) {
            int idx = tid + it * 256;
            int row = idx >> 4;
            int d4 = (idx & 15) << 2;
            float4 kf = *(const float4*)&Kb[((size_t)(kt * 64 + row) << 6) + d4];
            KPs[(d4 + 0) * 64 + row] = kf.x;
            KPs[(d4 + 1) * 64 + row] = kf.y;
            KPs[(d4 + 2) * 64 + row] = kf.z;
            KPs[(d4 + 3) * 64 + row] = kf.w;
            float4 vf = *(const float4*)&Vb[((size_t)(kt * 64 + row) << 6) + d4];
            *(float4*)&Vs[row * 64 + d4] = vf;
        }
        __syncthreads();

        float sacc[4][4] = {};
#pragma unroll
        for (int kk = 0; kk < 64; kk++) {
            float4 qa = *(const float4*)&Qs[kk * 64 + (ty << 2)];
            float4 ka = *(const float4*)&KPs[kk * 64 + (tx << 2)];
            float aa[4] = {qa.x, qa.y, qa.z, qa.w};
            float bb2[4] = {ka.x, ka.y, ka.z, ka.w};
#pragma unroll
            for (int i = 0; i < 4; i++)
#pragma unroll
                for (int j = 0; j < 4; j++)
                    sacc[i][j] = fmaf(aa[i], bb2[j], sacc[i][j]);
        }

        float vneg[4];
#pragma unroll
        for (int j = 0; j < 4; j++) {
            int key = kt * 64 + (tx << 2) + j;
            vneg[j] = vmask[b * SDIM + key] ? 0.0f : NEGV;
        }
#pragma unroll
        for (int i = 0; i < 4; i++) {
            int qrow = qt * 64 + (ty << 2) + i;
#pragma unroll
            for (int j = 0; j < 4; j++) {
                int key = kt * 64 + (tx << 2) + j;
                float s = sacc[i][j] * 0.125f - vneg[j];
                if (key > qrow) s -= NEGV;
                sacc[i][j] = s;
            }
        }

#pragma unroll
        for (int i = 0; i < 4; i++) {
            float tmax = fmaxf(fmaxf(sacc[i][0], sacc[i][1]),
                               fmaxf(sacc[i][2], sacc[i][3]));
#pragma unroll
            for (int off = 8; off >= 1; off >>= 1)
                tmax = fmaxf(tmax, __shfl_xor_sync(0xffffffffu, tmax, off));
            float mn = fmaxf(m_i[i], tmax);
            float corr = __expf(m_i[i] - mn);
            float rs = 0.0f;
#pragma unroll
            for (int j = 0; j < 4; j++) {
                float p = __expf(sacc[i][j] - mn);
                sacc[i][j] = p;
                rs += p;
            }
#pragma unroll
            for (int off = 8; off >= 1; off >>= 1)
                rs += __shfl_xor_sync(0xffffffffu, rs, off);
            l_i[i] = l_i[i] * corr + rs;
            m_i[i] = mn;
#pragma unroll
            for (int d = 0; d < 4; d++) o_acc[i][d] *= corr;
        }

        __syncthreads();
#pragma unroll
        for (int i = 0; i < 4; i++)
#pragma unroll
            for (int j = 0; j < 4; j++)
                KPs[((tx << 2) + j) * 64 + (ty << 2) + i] = sacc[i][j];
        __syncthreads();

#pragma unroll
        for (int jj = 0; jj < 64; jj++) {
            float4 pa = *(const float4*)&KPs[jj * 64 + (ty << 2)];
            float4 va = *(const float4*)&Vs[jj * 64 + (tx << 2)];
            float pp[4] = {pa.x, pa.y, pa.z, pa.w};
            float vv[4] = {va.x, va.y, va.z, va.w};
#pragma unroll
            for (int i = 0; i < 4; i++)
#pragma unroll
                for (int d = 0; d < 4; d++)
                    o_acc[i][d] = fmaf(pp[i], vv[d], o_acc[i][d]);
        }
    };

    for (int kt = 0; kt <= qt; kt++) process_tile(kt);

    bool deg = false;
#pragma unroll
    for (int i = 0; i < 4; i++) deg |= (m_i[i] < -1e11f);
    if (deg) s_flag = 1;
    __syncthreads();
    if (s_flag) {
        for (int kt = qt + 1; kt < 16; kt++) process_tile(kt);
    }

    float* Ob = g_scratch + oOff;
#pragma unroll
    for (int i = 0; i < 4; i++) {
        int qrow = qt * 64 + (ty << 2) + i;
        float inv = 1.0f / l_i[i];
        float4 cc;
        cc.x = o_acc[i][0] * inv;
        cc.y = o_acc[i][1] * inv;
        cc.z = o_acc[i][2] * inv;
        cc.w = o_acc[i][3] * inv;
        *(float4*)&Ob[((size_t)(b * SDIM + qrow) << 10) + (h << 6) + (tx << 2)] = cc;
    }
}

// ---------------------------------------------------------------------------
extern "C" void kernel_launch(void* const* d_in, const int* in_sizes, int n_in,
                              void* d_out, int out_size)
{
    const float* q     = (const float*)d_in[0];
    const float* k     = (const float*)d_in[1];
    const float* v     = (const float*)d_in[2];
    const int*   vmask = (const int*)  d_in[3];
    const int*   qmask = (const int*)  d_in[4];
    // d_in[5] = a_mask (causal tril) -- implemented analytically
    const float* Wq = (const float*)d_in[6];
    const float* bq = (const float*)d_in[7];
    const float* Wk = (const float*)d_in[8];
    const float* bk = (const float*)d_in[9];
    const float* Wv = (const float*)d_in[10];
    const float* bv = (const float*)d_in[11];
    const float* Wo = (const float*)d_in[12];
    const float* bo = (const float*)d_in[13];
    float* out = (float*)d_out;

    const unsigned QW = 0u, KW = SEG, VW = 2u * SEG, OB = 3u * SEG;

    dim3 grid(8, 32), blk(256);
    gemmTC<0><<<grid, blk>>>(q, 0u, Wq, bq, nullptr, nullptr, QW);
    gemmTC<0><<<grid, blk>>>(k, 0u, Wk, bk, nullptr, nullptr, KW);
    gemmTC<0><<<grid, blk>>>(v, 0u, Wv, bv, nullptr, nullptr, VW);
    attn64<<<dim3(16, 64), blk>>>(QW, KW, VW, OB, vmask);
    gemmTC<1><<<grid, blk>>>(nullptr, OB, Wo, bo, qmask, out, 0u);
}